// round 3
// baseline (speedup 1.0000x reference)
#include <cuda_runtime.h>

// Problem constants (fixed by the reference):
//   q: (32, 8, 512, 64) f32   k: (32, 8, 64, 512) f32   v: (32, 8, 512, 64) f32
//   attn_mask: (8, 512, 512) bool; True => masked out (-inf). Serialized dtype
//   unknown (uint8 vs int32) -> detected at runtime by a prologue kernel.
//   out: (32, 8, 512, 64) f32
static constexpr int H_   = 8;
static constexpr int C_   = 4;
static constexpr int L_   = 512;
static constexpr int D_   = 64;
static constexpr int QT   = 128;  // q rows per CTA
static constexpr int KT   = 64;   // keys per chunk
static constexpr int NCH  = L_ / KT;  // 8
static constexpr int NTHR = 128;

// SMEM layout (dynamic):
//   Qs[QT][65]  (pad 65 so per-thread row reads are conflict-free)
//   Ks[D][KT]   (d-major, matches k's gmem layout)
//   Vs[KT][D]
//   Ps[QT][65]  (per-thread private row: p bounce buffer, no sync needed)
static constexpr int QS_OFF = 0;
static constexpr int KS_OFF = QS_OFF + QT * 65;
static constexpr int VS_OFF = KS_OFF + D_ * KT;
static constexpr int PS_OFF = VS_OFF + KT * D_;
static constexpr int SMEM_FLOATS = PS_OFF + QT * 65;
static constexpr int SMEM_BYTES  = SMEM_FLOATS * 4;   // 99328 bytes

extern __shared__ float smem_dyn[];

// 0 = mask elements are int32 (one int per bool), 1 = packed uint8 bytes.
__device__ int g_mask_is_u8;

__global__ void detect_mask_dtype(const unsigned int* __restrict__ M32)
{
    __shared__ int found;
    if (threadIdx.x == 0) found = 0;
    __syncthreads();
    // If dtype is int32, every word is 0 or 1. If packed uint8 (random 0/1
    // bytes), most words have a byte set above lane 0.
    unsigned int w = M32[threadIdx.x];
    if (w > 1u) atomicOr(&found, 1);
    __syncthreads();
    if (threadIdx.x == 0) g_mask_is_u8 = found;
}

__global__ __launch_bounds__(NTHR, 2)
void attn_fwd_simt(const float* __restrict__ Q,
                   const float* __restrict__ K,
                   const float* __restrict__ V,
                   const unsigned char* __restrict__ M,
                   float* __restrict__ O)
{
    const int qt  = blockIdx.x;          // 0..3
    const int gh  = blockIdx.y;          // 0..255  (= g*H + h)
    const int g   = gh / H_;
    const int b   = g / C_;
    const int tid = threadIdx.x;
    const int l   = qt * QT + tid;       // this thread's q row

    float* Qs = smem_dyn + QS_OFF;
    float* Ks = smem_dyn + KS_OFF;
    float* Vs = smem_dyn + VS_OFF;
    float* Ps = smem_dyn + PS_OFF;

    const float* qg = Q + (size_t)gh * L_ * D_;
    const float* kg = K + (size_t)gh * D_ * L_;
    const float* vg = V + (size_t)gh * L_ * D_;

    const int mask_u8 = g_mask_is_u8;
    const size_t mrow = (size_t)b * L_ * L_ + (size_t)l * L_;
    const unsigned char* mg8 = M + mrow;              // uint8 path
    const int* mg32 = (const int*)M + mrow;           // int32 path

    // ---- load Q tile into padded SMEM (coalesced read, scalar padded write)
    {
        const float4* src = (const float4*)(qg + (size_t)qt * QT * D_);
        #pragma unroll
        for (int it = 0; it < (QT * D_ / 4) / NTHR; it++) {
            int i = it * NTHR + tid;
            float4 t = src[i];
            int r = (i * 4) / D_;
            int c = (i * 4) % D_;
            float* dst = Qs + r * 65 + c;
            dst[0] = t.x; dst[1] = t.y; dst[2] = t.z; dst[3] = t.w;
        }
    }

    float out[D_];
    #pragma unroll
    for (int d = 0; d < D_; d++) out[d] = 0.f;
    float mrun = -1e30f;
    float lrun = 0.f;
    const float scale = 0.125f;   // 64^-0.5

    for (int ch = 0; ch < NCH; ch++) {
        const int m0 = ch * KT;

        __syncthreads();   // previous chunk's Ks/Vs consumers done
        // Ks[d][j] = k[d][m0+j]
        for (int i = tid; i < D_ * KT / 4; i += NTHR) {
            int d = i / (KT / 4);
            int j = (i % (KT / 4)) * 4;
            *(float4*)(Ks + d * KT + j) =
                *(const float4*)(kg + (size_t)d * L_ + m0 + j);
        }
        // Vs[j][d] = v[m0+j][d]
        for (int i = tid; i < KT * D_ / 4; i += NTHR) {
            *(float4*)(Vs + i * 4) =
                *(const float4*)(vg + (size_t)m0 * D_ + i * 4);
        }
        __syncthreads();

        // ---- scores: s[j] = sum_d Qs[tid][d] * Ks[d][j]
        float s[KT];
        #pragma unroll
        for (int j = 0; j < KT; j++) s[j] = 0.f;
        #pragma unroll 4
        for (int d = 0; d < D_; d++) {
            float qd = Qs[tid * 65 + d];
            #pragma unroll
            for (int jg = 0; jg < KT / 4; jg++) {
                float4 kk = *(const float4*)(Ks + d * KT + jg * 4);
                s[4 * jg + 0] += qd * kk.x;
                s[4 * jg + 1] += qd * kk.y;
                s[4 * jg + 2] += qd * kk.z;
                s[4 * jg + 3] += qd * kk.w;
            }
        }

        // ---- build 64-bit mask for this chunk (bit j = masked)
        unsigned long long mbits = 0ull;
        if (mask_u8) {
            #pragma unroll
            for (int w = 0; w < KT / 4; w++) {
                unsigned int mw = *(const unsigned int*)(mg8 + m0 + w * 4);
                #pragma unroll
                for (int bq = 0; bq < 4; bq++)
                    if ((mw >> (bq * 8)) & 0xFF)
                        mbits |= 1ull << (w * 4 + bq);
            }
        } else {
            #pragma unroll
            for (int w = 0; w < KT / 4; w++) {
                int4 mi = *(const int4*)(mg32 + m0 + w * 4);
                if (mi.x) mbits |= 1ull << (w * 4 + 0);
                if (mi.y) mbits |= 1ull << (w * 4 + 1);
                if (mi.z) mbits |= 1ull << (w * 4 + 2);
                if (mi.w) mbits |= 1ull << (w * 4 + 3);
            }
        }

        // ---- mask + scale (True => -inf)
        #pragma unroll
        for (int j = 0; j < KT; j++) {
            bool msk = (mbits >> j) & 1ull;
            s[j] = msk ? -1e30f : s[j] * scale;
        }

        // ---- online softmax
        float mloc = -1e30f;
        #pragma unroll
        for (int j = 0; j < KT; j++) mloc = fmaxf(mloc, s[j]);
        float mnew = fmaxf(mrun, mloc);
        float corr = __expf(mrun - mnew);
        float ladd = 0.f;
        #pragma unroll
        for (int j = 0; j < KT; j++) {
            float p = __expf(s[j] - mnew);
            ladd += p;
            Ps[tid * 65 + j] = p;   // private row, no sync needed
        }
        lrun = lrun * corr + ladd;
        mrun = mnew;
        #pragma unroll
        for (int d = 0; d < D_; d++) out[d] *= corr;

        // ---- PV: out[d] += p[j] * Vs[j][d]
        #pragma unroll 4
        for (int j = 0; j < KT; j++) {
            float pj = Ps[tid * 65 + j];
            #pragma unroll
            for (int dg = 0; dg < D_ / 4; dg++) {
                float4 vv = *(const float4*)(Vs + j * D_ + dg * 4);
                out[4 * dg + 0] += pj * vv.x;
                out[4 * dg + 1] += pj * vv.y;
                out[4 * dg + 2] += pj * vv.z;
                out[4 * dg + 3] += pj * vv.w;
            }
        }
    }

    // ---- normalize + write
    float inv = 1.f / lrun;
    float* og = O + (size_t)gh * L_ * D_ + (size_t)l * D_;
    #pragma unroll
    for (int dg = 0; dg < D_ / 4; dg++) {
        float4 t;
        t.x = out[4 * dg + 0] * inv;
        t.y = out[4 * dg + 1] * inv;
        t.z = out[4 * dg + 2] * inv;
        t.w = out[4 * dg + 3] * inv;
        *(float4*)(og + dg * 4) = t;
    }
}

extern "C" void kernel_launch(void* const* d_in, const int* in_sizes, int n_in,
                              void* d_out, int out_size)
{
    const float* q = (const float*)d_in[0];
    const float* k = (const float*)d_in[1];
    const float* v = (const float*)d_in[2];
    const unsigned char* m = (const unsigned char*)d_in[3];
    float* o = (float*)d_out;

    cudaFuncSetAttribute(attn_fwd_simt,
                         cudaFuncAttributeMaxDynamicSharedMemorySize,
                         SMEM_BYTES);

    detect_mask_dtype<<<1, 256>>>((const unsigned int*)m);

    dim3 grid(L_ / QT, 32 * H_);   // (4, 256)
    attn_fwd_simt<<<grid, NTHR, SMEM_BYTES>>>(q, k, v, m, o);
}

// round 8
// speedup vs baseline: 1.1621x; 1.1621x over previous
#include <cuda_runtime.h>

// q: (32, 8, 512, 64) f32   k: (32, 8, 64, 512) f32   v: (32, 8, 512, 64) f32
// attn_mask: (8, 512, 512) bool (dtype u8 vs i32 detected at runtime); True => -inf
// out: (32, 8, 512, 64) f32
static constexpr int H_   = 8;
static constexpr int C_   = 4;
static constexpr int L_   = 512;
static constexpr int D_   = 64;
static constexpr int QR   = 64;        // q rows per CTA
static constexpr int KT   = 64;        // keys per chunk
static constexpr int NCH  = L_ / KT;   // 8
static constexpr int NTHR = 128;

// SMEM: Qts[64][68] (d-major, padded) | Ks[64][64] (d-major) | Vs[64][64] (j-major)
static constexpr int QTS_OFF = 0;
static constexpr int KS_OFF  = QTS_OFF + 64 * 68;
static constexpr int VS_OFF  = KS_OFF + 64 * 64;
static constexpr int SMEM_FLOATS = VS_OFF + 64 * 64;
static constexpr int SMEM_BYTES  = SMEM_FLOATS * 4;   // 50176 B

extern __shared__ float smem_dyn[];

// 0 = mask elements are int32, 1 = packed uint8.
__device__ int g_mask_is_u8;

__global__ void detect_mask_dtype(const unsigned int* __restrict__ M32)
{
    __shared__ int found;
    if (threadIdx.x == 0) found = 0;
    __syncthreads();
    unsigned int w = M32[threadIdx.x];   // int32 bools are always 0 or 1
    if (w > 1u) atomicOr(&found, 1);
    __syncthreads();
    if (threadIdx.x == 0) g_mask_is_u8 = found;
}

__global__ __launch_bounds__(NTHR, 3)
void attn_fwd_rt(const float* __restrict__ Q,
                 const float* __restrict__ K,
                 const float* __restrict__ V,
                 const unsigned char* __restrict__ M,
                 float* __restrict__ O)
{
    const int qt  = blockIdx.x;          // 0..7
    const int gh  = blockIdx.y;          // 0..255
    const int b   = (gh / H_) / C_;
    const int tid = threadIdx.x;
    const int tr  = tid >> 3;            // 0..15 : row group
    const int tc  = tid & 7;             // 0..7  : col group
    const int q0  = qt * QR;
    const int r0  = q0 + tr * 4;         // this thread's first global q row

    float* Qts = smem_dyn + QTS_OFF;
    float* Ks  = smem_dyn + KS_OFF;
    float* Vs  = smem_dyn + VS_OFF;

    const float* qg = Q + (size_t)gh * L_ * D_;
    const float* kg = K + (size_t)gh * D_ * L_;
    const float* vg = V + (size_t)gh * L_ * D_;

    const int mask_u8 = g_mask_is_u8;
    const unsigned char* mg8 = M + ((size_t)b * L_ + r0) * L_;
    const int* mg32 = (const int*)M + ((size_t)b * L_ + r0) * L_;

    // ---- load Q tile, transposed to d-major (coalesced gmem read)
    {
        const float4* src = (const float4*)(qg + (size_t)q0 * D_);
        #pragma unroll
        for (int it = 0; it < 8; it++) {
            int i = it * NTHR + tid;        // 0..1023
            float4 t = src[i];
            int r = i >> 4;                 // 0..63
            int c = (i & 15) * 4;
            Qts[(c + 0) * 68 + r] = t.x;
            Qts[(c + 1) * 68 + r] = t.y;
            Qts[(c + 2) * 68 + r] = t.z;
            Qts[(c + 3) * 68 + r] = t.w;
        }
    }

    float out[4][8];                       // [ri][di]
    #pragma unroll
    for (int ri = 0; ri < 4; ri++)
        #pragma unroll
        for (int di = 0; di < 8; di++) out[ri][di] = 0.f;
    float mrun[4] = {-1e30f, -1e30f, -1e30f, -1e30f};
    float lrun[4] = {0.f, 0.f, 0.f, 0.f};
    const float scale = 0.125f;            // 64^-0.5

    for (int ch = 0; ch < NCH; ch++) {
        const int m0 = ch * KT;

        __syncthreads();                   // prev chunk's Ks/Vs consumers done
        #pragma unroll
        for (int it = 0; it < 8; it++) {   // Ks[d][j] = k[d][m0+j]
            int i = it * NTHR + tid;       // 64 d x 16 float4
            int d = i >> 4;
            int j4 = (i & 15) << 2;
            *(float4*)(Ks + d * 64 + j4) =
                *(const float4*)(kg + (size_t)d * L_ + m0 + j4);
        }
        #pragma unroll
        for (int it = 0; it < 8; it++) {   // Vs[j][d] = v[m0+j][d]
            int i = it * NTHR + tid;
            *(float4*)(Vs + i * 4) =
                *(const float4*)(vg + (size_t)m0 * D_ + i * 4);
        }
        __syncthreads();

        // ---- QK: s[ji][ri] = sum_d q[r0+ri][d] * k[d][m0+tc*8+ji]
        float s[8][4];
        #pragma unroll
        for (int ji = 0; ji < 8; ji++)
            #pragma unroll
            for (int ri = 0; ri < 4; ri++) s[ji][ri] = 0.f;

        #pragma unroll 4
        for (int d = 0; d < 64; d++) {
            float4 qv = *(const float4*)(Qts + d * 68 + tr * 4);
            float4 k0 = *(const float4*)(Ks + d * 64 + tc * 8);
            float4 k1 = *(const float4*)(Ks + d * 64 + tc * 8 + 4);
            float qa[4] = {qv.x, qv.y, qv.z, qv.w};
            float ka[8] = {k0.x, k0.y, k0.z, k0.w, k1.x, k1.y, k1.z, k1.w};
            #pragma unroll
            for (int ji = 0; ji < 8; ji++)
                #pragma unroll
                for (int ri = 0; ri < 4; ri++)
                    s[ji][ri] += qa[ri] * ka[ji];
        }

        // ---- mask + scale (True => -inf)
        #pragma unroll
        for (int ri = 0; ri < 4; ri++) {
            if (mask_u8) {
                const unsigned char* mp = mg8 + (size_t)ri * L_ + m0 + tc * 8;
                unsigned int w0 = *(const unsigned int*)(mp);
                unsigned int w1 = *(const unsigned int*)(mp + 4);
                #pragma unroll
                for (int ji = 0; ji < 4; ji++) {
                    bool k0m = (w0 >> (ji * 8)) & 0xFF;
                    bool k1m = (w1 >> (ji * 8)) & 0xFF;
                    s[ji][ri]     = k0m ? -1e30f : s[ji][ri] * scale;
                    s[ji + 4][ri] = k1m ? -1e30f : s[ji + 4][ri] * scale;
                }
            } else {
                const int* mp = mg32 + (size_t)ri * L_ + m0 + tc * 8;
                int4 a = *(const int4*)(mp);
                int4 c2 = *(const int4*)(mp + 4);
                s[0][ri] = a.x  ? -1e30f : s[0][ri] * scale;
                s[1][ri] = a.y  ? -1e30f : s[1][ri] * scale;
                s[2][ri] = a.z  ? -1e30f : s[2][ri] * scale;
                s[3][ri] = a.w  ? -1e30f : s[3][ri] * scale;
                s[4][ri] = c2.x ? -1e30f : s[4][ri] * scale;
                s[5][ri] = c2.y ? -1e30f : s[5][ri] * scale;
                s[6][ri] = c2.z ? -1e30f : s[6][ri] * scale;
                s[7][ri] = c2.w ? -1e30f : s[7][ri] * scale;
            }
        }

        // ---- online softmax (reduce across the 8-lane key group)
        #pragma unroll
        for (int ri = 0; ri < 4; ri++) {
            float mx = s[0][ri];
            #pragma unroll
            for (int ji = 1; ji < 8; ji++) mx = fmaxf(mx, s[ji][ri]);
            mx = fmaxf(mx, __shfl_xor_sync(0xffffffffu, mx, 1));
            mx = fmaxf(mx, __shfl_xor_sync(0xffffffffu, mx, 2));
            mx = fmaxf(mx, __shfl_xor_sync(0xffffffffu, mx, 4));
            float mnew = fmaxf(mrun[ri], mx);
            float corr = __expf(mrun[ri] - mnew);
            mrun[ri] = mnew;
            float ls = 0.f;
            #pragma unroll
            for (int ji = 0; ji < 8; ji++) {
                float p = __expf(s[ji][ri] - mnew);
                s[ji][ri] = p;
                ls += p;
            }
            ls += __shfl_xor_sync(0xffffffffu, ls, 1);
            ls += __shfl_xor_sync(0xffffffffu, ls, 2);
            ls += __shfl_xor_sync(0xffffffffu, ls, 4);
            lrun[ri] = lrun[ri] * corr + ls;
            #pragma unroll
            for (int di = 0; di < 8; di++) out[ri][di] *= corr;
        }

        // ---- PV: out[ri][di] += p[ri][j] * Vs[j][tc*8+di], p via shfl broadcast
        for (int jc = 0; jc < 8; jc++) {
            #pragma unroll
            for (int ji = 0; ji < 8; ji++) {
                int j = jc * 8 + ji;
                float p0 = __shfl_sync(0xffffffffu, s[ji][0], jc, 8);
                float p1 = __shfl_sync(0xffffffffu, s[ji][1], jc, 8);
                float p2 = __shfl_sync(0xffffffffu, s[ji][2], jc, 8);
                float p3 = __shfl_sync(0xffffffffu, s[ji][3], jc, 8);
                float4 v0 = *(const float4*)(Vs + j * 64 + tc * 8);
                float4 v1 = *(const float4*)(Vs + j * 64 + tc * 8 + 4);
                float va[8] = {v0.x, v0.y, v0.z, v0.w, v1.x, v1.y, v1.z, v1.w};
                #pragma unroll
                for (int di = 0; di < 8; di++) {
                    out[0][di] += p0 * va[di];
                    out[1][di] += p1 * va[di];
                    out[2][di] += p2 * va[di];
                    out[3][di] += p3 * va[di];
                }
            }
        }
    }

    // ---- normalize + write
    #pragma unroll
    for (int ri = 0; ri < 4; ri++) {
        float inv = 1.f / lrun[ri];
        float* og = O + ((size_t)gh * L_ + r0 + ri) * D_ + tc * 8;
        float4 t0, t1;
        t0.x = out[ri][0] * inv; t0.y = out[ri][1] * inv;
        t0.z = out[ri][2] * inv; t0.w = out[ri][3] * inv;
        t1.x = out[ri][4] * inv; t1.y = out[ri][5] * inv;
        t1.z = out[ri][6] * inv; t1.w = out[ri][7] * inv;
        *(float4*)(og)     = t0;
        *(float4*)(og + 4) = t1;
    }
}

extern "C" void kernel_launch(void* const* d_in, const int* in_sizes, int n_in,
                              void* d_out, int out_size)
{
    const float* q = (const float*)d_in[0];
    const float* k = (const float*)d_in[1];
    const float* v = (const float*)d_in[2];
    const unsigned char* m = (const unsigned char*)d_in[3];
    float* o = (float*)d_out;

    cudaFuncSetAttribute(attn_fwd_rt,
                         cudaFuncAttributeMaxDynamicSharedMemorySize,
                         SMEM_BYTES);

    detect_mask_dtype<<<1, 256>>>((const unsigned int*)m);

    dim3 grid(L_ / QR, 32 * H_);   // (8, 256)
    attn_fwd_rt<<<grid, NTHR, SMEM_BYTES>>>(q, k, v, m, o);
}

// round 11
// speedup vs baseline: 1.3557x; 1.1666x over previous
#include <cuda_runtime.h>
#include <cstdint>

// q: (32, 8, 512, 64) f32   k: (32, 8, 64, 512) f32   v: (32, 8, 512, 64) f32
// attn_mask: (8, 512, 512) bool (u8 vs i32 detected at runtime); True => -inf
// out: (32, 8, 512, 64) f32
static constexpr int H_   = 8;
static constexpr int C_   = 4;
static constexpr int L_   = 512;
static constexpr int D_   = 64;
static constexpr int QR   = 128;       // q rows per CTA (4 warps x 32 rows)
static constexpr int KT   = 64;        // keys per chunk
static constexpr int NCH  = L_ / KT;   // 8
static constexpr int NTHR = 128;

// SMEM (bytes):
//  Qhl : float2[128][66]  (hi,lo) pairs, row-major q
//  Khl : float2[64][66]   (hi,lo) pairs, d-major k
//  Vp  : float2[32][66]   (V[j],V[j+4]) row pairs, tf32-rounded
//  Ps  : float[128][68]   P tile (stride 68 -> conflict-free frag reads)
//  Ms  : uchar[128][64]   mask bytes
static constexpr int QHL_F2 = 128 * 66;
static constexpr int KHL_F2 = 64 * 66;
static constexpr int VP_F2  = 32 * 66;
static constexpr int PS_F   = 128 * 68;
static constexpr int MS_B   = 128 * 64;
static constexpr int OFF_QHL = 0;
static constexpr int OFF_KHL = OFF_QHL + QHL_F2 * 8;
static constexpr int OFF_VP  = OFF_KHL + KHL_F2 * 8;
static constexpr int OFF_PS  = OFF_VP + VP_F2 * 8;
static constexpr int OFF_MS  = OFF_PS + PS_F * 4;
static constexpr int SMEM_BYTES = OFF_MS + MS_B;   // 161280

extern __shared__ char smem_raw[];

// 0 = mask elements are int32, 1 = packed uint8.
__device__ int g_mask_is_u8;

__global__ void detect_mask_dtype(const unsigned int* __restrict__ M32)
{
    __shared__ int found;
    if (threadIdx.x == 0) found = 0;
    __syncthreads();
    unsigned int w = M32[threadIdx.x];   // int32 bools are always 0 or 1
    if (w > 1u) atomicOr(&found, 1);
    __syncthreads();
    if (threadIdx.x == 0) g_mask_is_u8 = found;
}

__device__ __forceinline__ float tf32hi(float x) {
    return __uint_as_float(__float_as_uint(x) & 0xFFFFE000u);
}
__device__ __forceinline__ float tf32rna(float x) {
    uint32_t u;
    asm("cvt.rna.tf32.f32 %0, %1;" : "=r"(u) : "f"(x));
    return __uint_as_float(u);
}
__device__ __forceinline__ void mma_tf32(float c[4],
                                         float a0, float a1, float a2, float a3,
                                         float b0, float b1)
{
    asm volatile(
        "mma.sync.aligned.m16n8k8.row.col.f32.tf32.tf32.f32 "
        "{%0,%1,%2,%3}, {%4,%5,%6,%7}, {%8,%9}, {%0,%1,%2,%3};\n"
        : "+f"(c[0]), "+f"(c[1]), "+f"(c[2]), "+f"(c[3])
        : "r"(__float_as_uint(a0)), "r"(__float_as_uint(a1)),
          "r"(__float_as_uint(a2)), "r"(__float_as_uint(a3)),
          "r"(__float_as_uint(b0)), "r"(__float_as_uint(b1)));
}

__global__ __launch_bounds__(NTHR, 1)
void attn_fwd_mma(const float* __restrict__ Q,
                  const float* __restrict__ K,
                  const float* __restrict__ V,
                  const unsigned char* __restrict__ M,
                  float* __restrict__ O)
{
    float2* Qhl = (float2*)(smem_raw + OFF_QHL);
    float2* Khl = (float2*)(smem_raw + OFF_KHL);
    float2* Vp  = (float2*)(smem_raw + OFF_VP);
    float*  Ps  = (float*)(smem_raw + OFF_PS);
    unsigned char* Ms = (unsigned char*)(smem_raw + OFF_MS);

    const int qt   = blockIdx.x;         // 0..3
    const int gh   = blockIdx.y;         // 0..255
    const int b    = (gh / H_) / C_;
    const int tid  = threadIdx.x;
    const int w    = tid >> 5;           // warp 0..3 -> rows w*32..+31
    const int lane = tid & 31;
    const int rr   = lane >> 2;          // 0..7
    const int cc   = lane & 3;           // 0..3

    const float* qg = Q + (size_t)gh * L_ * D_;
    const float* kg = K + (size_t)gh * D_ * L_;
    const float* vg = V + (size_t)gh * L_ * D_;
    const int mask_u8 = g_mask_is_u8;
    const unsigned char* m8base = M + (size_t)b * L_ * L_;
    const int* m32base = (const int*)M + (size_t)b * L_ * L_;

    // ---- stage Q (hi,lo) once: rows qt*128..+127
    {
        const float4* src = (const float4*)(qg + (size_t)qt * QR * D_);
        #pragma unroll
        for (int it = 0; it < 16; it++) {
            int i = it * NTHR + tid;          // 0..2047 float4s
            float4 t = src[i];
            int r = i >> 4;                   // /16
            int c = (i & 15) * 4;
            float va[4] = {t.x, t.y, t.z, t.w};
            #pragma unroll
            for (int e = 0; e < 4; e++) {
                float hi = tf32hi(va[e]);
                Qhl[r * 66 + c + e] = make_float2(hi, va[e] - hi);
            }
        }
    }

    float sacc[2][8][4];
    float oacc[2][8][4];
    #pragma unroll
    for (int mt = 0; mt < 2; mt++)
        #pragma unroll
        for (int nt = 0; nt < 8; nt++)
            #pragma unroll
            for (int e = 0; e < 4; e++) oacc[mt][nt][e] = 0.f;
    float mrun[2][2] = {{-1e30f, -1e30f}, {-1e30f, -1e30f}};
    float lrun[2][2] = {{0.f, 0.f}, {0.f, 0.f}};
    const float scale = 0.125f;

    for (int ch = 0; ch < NCH; ch++) {
        const int m0 = ch * KT;
        __syncthreads();   // previous chunk consumers done

        // ---- stage K (hi,lo): Khl[d][j]
        #pragma unroll
        for (int it = 0; it < 8; it++) {
            int i = it * NTHR + tid;          // 64 d x 16 float4
            int d = i >> 4;
            int j = (i & 15) * 4;
            float4 t = *(const float4*)(kg + (size_t)d * L_ + m0 + j);
            float va[4] = {t.x, t.y, t.z, t.w};
            #pragma unroll
            for (int e = 0; e < 4; e++) {
                float hi = tf32hi(va[e]);
                Khl[d * 66 + j + e] = make_float2(hi, va[e] - hi);
            }
        }
        // ---- stage V row-paired + tf32 round: Vp[jj*4+q][d] = (V[j], V[j+4])
        #pragma unroll
        for (int it = 0; it < 4; it++) {
            int i = it * NTHR + tid;          // 32 pr x 16 float4-groups
            int pr = i >> 4;                  // 0..31
            int d4 = (i & 15) * 4;
            int jj = pr >> 2, q = pr & 3;
            int j0 = m0 + jj * 8 + q;
            float4 ta = *(const float4*)(vg + (size_t)j0 * D_ + d4);
            float4 tb = *(const float4*)(vg + (size_t)(j0 + 4) * D_ + d4);
            float aa[4] = {ta.x, ta.y, ta.z, ta.w};
            float bb[4] = {tb.x, tb.y, tb.z, tb.w};
            #pragma unroll
            for (int e = 0; e < 4; e++)
                Vp[pr * 66 + d4 + e] = make_float2(tf32rna(aa[e]), tf32rna(bb[e]));
        }
        // ---- stage mask bytes: Ms[lr][j]
        if (mask_u8) {
            #pragma unroll
            for (int it = 0; it < 16; it++) {
                int i = it * NTHR + tid;      // 128 rows x 16 words
                int r = i >> 4, wc = i & 15;
                unsigned int mw = *(const unsigned int*)
                    (m8base + (size_t)(qt * QR + r) * L_ + m0 + wc * 4);
                ((unsigned int*)Ms)[r * 16 + wc] = mw;
            }
        } else {
            #pragma unroll
            for (int it = 0; it < 16; it++) {
                int i = it * NTHR + tid;
                int r = i >> 4, wc = i & 15;
                const int* mp = m32base + (size_t)(qt * QR + r) * L_ + m0 + wc * 4;
                int4 mi = *(const int4*)mp;
                unsigned int mw = (mi.x ? 1u : 0u) | (mi.y ? 0x100u : 0u)
                                | (mi.z ? 0x10000u : 0u) | (mi.w ? 0x1000000u : 0u);
                ((unsigned int*)Ms)[r * 16 + wc] = mw;
            }
        }
        __syncthreads();

        // ---- QK: 3xTF32 (hh + hl + lh)
        #pragma unroll
        for (int mt = 0; mt < 2; mt++)
            #pragma unroll
            for (int nt = 0; nt < 8; nt++)
                #pragma unroll
                for (int e = 0; e < 4; e++) sacc[mt][nt][e] = 0.f;

        #pragma unroll
        for (int kk = 0; kk < 8; kk++) {
            float2 aq[2][4];
            #pragma unroll
            for (int mt = 0; mt < 2; mt++) {
                int r = w * 32 + mt * 16 + rr;
                int c = kk * 8 + cc;
                aq[mt][0] = Qhl[r * 66 + c];
                aq[mt][1] = Qhl[(r + 8) * 66 + c];
                aq[mt][2] = Qhl[r * 66 + c + 4];
                aq[mt][3] = Qhl[(r + 8) * 66 + c + 4];
            }
            #pragma unroll
            for (int nt = 0; nt < 8; nt++) {
                float2 b0 = Khl[(kk * 8 + cc) * 66 + nt * 8 + rr];
                float2 b1 = Khl[(kk * 8 + cc + 4) * 66 + nt * 8 + rr];
                #pragma unroll
                for (int mt = 0; mt < 2; mt++) {
                    mma_tf32(sacc[mt][nt], aq[mt][0].x, aq[mt][1].x,
                             aq[mt][2].x, aq[mt][3].x, b0.y, b1.y);   // hi*lo
                    mma_tf32(sacc[mt][nt], aq[mt][0].y, aq[mt][1].y,
                             aq[mt][2].y, aq[mt][3].y, b0.x, b1.x);   // lo*hi
                    mma_tf32(sacc[mt][nt], aq[mt][0].x, aq[mt][1].x,
                             aq[mt][2].x, aq[mt][3].x, b0.x, b1.x);   // hi*hi
                }
            }
        }

        // ---- mask + scale + online softmax + P to SMEM
        #pragma unroll
        for (int mt = 0; mt < 2; mt++) {
            #pragma unroll
            for (int h = 0; h < 2; h++) {
                const int lr = w * 32 + mt * 16 + h * 8 + rr;   // CTA-local row
                float sv[8][2];
                float mx = -1e30f;
                #pragma unroll
                for (int nt = 0; nt < 8; nt++) {
                    unsigned short mw = *(const unsigned short*)
                        (Ms + lr * 64 + nt * 8 + 2 * cc);
                    float s0 = sacc[mt][nt][h * 2 + 0];
                    float s1 = sacc[mt][nt][h * 2 + 1];
                    sv[nt][0] = (mw & 0xFF)   ? -1e30f : s0 * scale;
                    sv[nt][1] = (mw >> 8)     ? -1e30f : s1 * scale;
                    mx = fmaxf(mx, fmaxf(sv[nt][0], sv[nt][1]));
                }
                mx = fmaxf(mx, __shfl_xor_sync(0xffffffffu, mx, 1, 4));
                mx = fmaxf(mx, __shfl_xor_sync(0xffffffffu, mx, 2, 4));
                float mnew = fmaxf(mrun[mt][h], mx);
                float corr = __expf(mrun[mt][h] - mnew);
                mrun[mt][h] = mnew;
                float ls = 0.f;
                #pragma unroll
                for (int nt = 0; nt < 8; nt++) {
                    float p0 = __expf(sv[nt][0] - mnew);
                    float p1 = __expf(sv[nt][1] - mnew);
                    ls += p0 + p1;
                    // tf32-round before smem so PV MMA sees rounded (not truncated)
                    *(float2*)(Ps + lr * 68 + nt * 8 + 2 * cc) =
                        make_float2(tf32rna(p0), tf32rna(p1));
                }
                ls += __shfl_xor_sync(0xffffffffu, ls, 1, 4);
                ls += __shfl_xor_sync(0xffffffffu, ls, 2, 4);
                lrun[mt][h] = lrun[mt][h] * corr + ls;
                #pragma unroll
                for (int nt = 0; nt < 8; nt++) {
                    oacc[mt][nt][h * 2 + 0] *= corr;
                    oacc[mt][nt][h * 2 + 1] *= corr;
                }
            }
        }
        __syncwarp();   // P stores visible to whole warp (rows are warp-private)

        // ---- PV: out += P x V  (single tf32, operands pre-rounded)
        #pragma unroll
        for (int jj = 0; jj < 8; jj++) {
            float ap[2][4];
            #pragma unroll
            for (int mt = 0; mt < 2; mt++) {
                int r = w * 32 + mt * 16 + rr;
                int c = jj * 8 + cc;
                ap[mt][0] = Ps[r * 68 + c];
                ap[mt][1] = Ps[(r + 8) * 68 + c];
                ap[mt][2] = Ps[r * 68 + c + 4];
                ap[mt][3] = Ps[(r + 8) * 68 + c + 4];
            }
            #pragma unroll
            for (int nt = 0; nt < 8; nt++) {
                float2 bp = Vp[(jj * 4 + cc) * 66 + nt * 8 + rr];
                #pragma unroll
                for (int mt = 0; mt < 2; mt++)
                    mma_tf32(oacc[mt][nt], ap[mt][0], ap[mt][1],
                             ap[mt][2], ap[mt][3], bp.x, bp.y);
            }
        }
    }

    // ---- epilogue: normalize + store
    #pragma unroll
    for (int mt = 0; mt < 2; mt++) {
        #pragma unroll
        for (int h = 0; h < 2; h++) {
            float inv = 1.f / lrun[mt][h];
            int grow = qt * QR + w * 32 + mt * 16 + h * 8 + rr;
            float* og = O + ((size_t)gh * L_ + grow) * D_;
            #pragma unroll
            for (int nt = 0; nt < 8; nt++) {
                float2 t;
                t.x = oacc[mt][nt][h * 2 + 0] * inv;
                t.y = oacc[mt][nt][h * 2 + 1] * inv;
                *(float2*)(og + nt * 8 + 2 * cc) = t;
            }
        }
    }
}

extern "C" void kernel_launch(void* const* d_in, const int* in_sizes, int n_in,
                              void* d_out, int out_size)
{
    const float* q = (const float*)d_in[0];
    const float* k = (const float*)d_in[1];
    const float* v = (const float*)d_in[2];
    const unsigned char* m = (const unsigned char*)d_in[3];
    float* o = (float*)d_out;

    cudaFuncSetAttribute(attn_fwd_mma,
                         cudaFuncAttributeMaxDynamicSharedMemorySize,
                         SMEM_BYTES);

    detect_mask_dtype<<<1, 256>>>((const unsigned int*)m);

    dim3 grid(L_ / QR, 32 * H_);   // (4, 256)
    attn_fwd_mma<<<grid, NTHR, SMEM_BYTES>>>(q, k, v, m, o);
}

// round 12
// speedup vs baseline: 2.9072x; 2.1444x over previous
#include <cuda_runtime.h>
#include <cstdint>

// q: (32, 8, 512, 64) f32   k: (32, 8, 64, 512) f32   v: (32, 8, 512, 64) f32
// attn_mask: (8, 512, 512) bool (u8 vs i32 detected at runtime); True => -inf
// out: (32, 8, 512, 64) f32
static constexpr int H_   = 8;
static constexpr int C_   = 4;
static constexpr int L_   = 512;
static constexpr int D_   = 64;
static constexpr int QR   = 128;       // q rows per CTA (8 warps x 16 rows)
static constexpr int KT   = 64;        // keys per chunk
static constexpr int NCH  = L_ / KT;   // 8
static constexpr int NTHR = 256;

// SMEM (floats):
//  Qs[128][68] raw q, row-major          (frag reads conflict-free: rr*4+cc)
//  Ks[64][72]  raw k, d-major            (frag reads conflict-free: cc*8+rr)
//  Vs[64][72]  raw v, j-major            (same)
//  Ps[128][68] P tile (tf32-rounded)
static constexpr int QS_OFF = 0;
static constexpr int KS_OFF = QS_OFF + 128 * 68;
static constexpr int VS_OFF = KS_OFF + 64 * 72;
static constexpr int PS_OFF = VS_OFF + 64 * 72;
static constexpr int SMEM_FLOATS = PS_OFF + 128 * 68;
static constexpr int SMEM_BYTES  = SMEM_FLOATS * 4;   // 106496 B -> 2 CTAs/SM

extern __shared__ float smem_f[];

// 0 = mask elements are int32, 1 = packed uint8.
__device__ int g_mask_is_u8;
// Packed mask bits: [b][row][chunk] -> u64, bit j = key (chunk*64+j) masked.
__device__ unsigned long long g_mbits[H_ * L_ * NCH];

__global__ void detect_mask_dtype(const unsigned int* __restrict__ M32)
{
    __shared__ int found;
    if (threadIdx.x == 0) found = 0;
    __syncthreads();
    unsigned int w = M32[threadIdx.x];   // int32 bools are always 0 or 1
    if (w > 1u) atomicOr(&found, 1);
    __syncthreads();
    if (threadIdx.x == 0) g_mask_is_u8 = found;
}

__global__ void pack_mask(const unsigned char* __restrict__ M)
{
    int idx = blockIdx.x * blockDim.x + threadIdx.x;   // 0 .. 8*512*8-1
    int ch  = idx & 7;
    int row = idx >> 3;                                // b*512 + l
    unsigned long long bits = 0ull;
    if (g_mask_is_u8) {
        const unsigned char* p = M + (size_t)row * L_ + ch * 64;
        #pragma unroll
        for (int w = 0; w < 4; w++) {
            uint4 t = ((const uint4*)p)[w];
            unsigned int ws[4] = {t.x, t.y, t.z, t.w};
            #pragma unroll
            for (int e = 0; e < 4; e++)
                #pragma unroll
                for (int bq = 0; bq < 4; bq++)
                    if ((ws[e] >> (bq * 8)) & 0xFF)
                        bits |= 1ull << (w * 16 + e * 4 + bq);
        }
    } else {
        const int* p = (const int*)M + (size_t)row * L_ + ch * 64;
        #pragma unroll
        for (int w = 0; w < 16; w++) {
            int4 t = ((const int4*)p)[w];
            if (t.x) bits |= 1ull << (w * 4 + 0);
            if (t.y) bits |= 1ull << (w * 4 + 1);
            if (t.z) bits |= 1ull << (w * 4 + 2);
            if (t.w) bits |= 1ull << (w * 4 + 3);
        }
    }
    g_mbits[idx] = bits;
}

__device__ __forceinline__ float tf32hi(float x) {
    return __uint_as_float(__float_as_uint(x) & 0xFFFFE000u);
}
__device__ __forceinline__ float tf32rna(float x) {
    uint32_t u;
    asm("cvt.rna.tf32.f32 %0, %1;" : "=r"(u) : "f"(x));
    return __uint_as_float(u);
}
__device__ __forceinline__ void mma_tf32(float c[4],
                                         float a0, float a1, float a2, float a3,
                                         float b0, float b1)
{
    asm volatile(
        "mma.sync.aligned.m16n8k8.row.col.f32.tf32.tf32.f32 "
        "{%0,%1,%2,%3}, {%4,%5,%6,%7}, {%8,%9}, {%0,%1,%2,%3};\n"
        : "+f"(c[0]), "+f"(c[1]), "+f"(c[2]), "+f"(c[3])
        : "r"(__float_as_uint(a0)), "r"(__float_as_uint(a1)),
          "r"(__float_as_uint(a2)), "r"(__float_as_uint(a3)),
          "r"(__float_as_uint(b0)), "r"(__float_as_uint(b1)));
}

__global__ __launch_bounds__(NTHR, 2)
void attn_fwd_mma2(const float* __restrict__ Q,
                   const float* __restrict__ K,
                   const float* __restrict__ V,
                   float* __restrict__ O)
{
    float* Qs = smem_f + QS_OFF;
    float* Ks = smem_f + KS_OFF;
    float* Vs = smem_f + VS_OFF;
    float* Ps = smem_f + PS_OFF;

    const int qt   = blockIdx.x;         // 0..3
    const int gh   = blockIdx.y;         // 0..255
    const int b    = (gh / H_) / C_;
    const int tid  = threadIdx.x;
    const int w    = tid >> 5;           // warp 0..7 -> rows w*16..+15
    const int lane = tid & 31;
    const int rr   = lane >> 2;          // 0..7
    const int cc   = lane & 3;           // 0..3

    const float* qg = Q + (size_t)gh * L_ * D_;
    const float* kg = K + (size_t)gh * D_ * L_;
    const float* vg = V + (size_t)gh * L_ * D_;

    // ---- stage Q raw (rows qt*128..+127), coalesced
    {
        const float4* src = (const float4*)(qg + (size_t)qt * QR * D_);
        #pragma unroll
        for (int it = 0; it < 8; it++) {
            int i = it * NTHR + tid;          // 0..2047 float4s
            float4 t = src[i];
            int r = i >> 4;
            int c = (i & 15) * 4;
            *(float4*)(Qs + r * 68 + c) = t;
        }
    }

    float sacc[8][4];
    float oacc[8][4];
    #pragma unroll
    for (int nt = 0; nt < 8; nt++)
        #pragma unroll
        for (int e = 0; e < 4; e++) oacc[nt][e] = 0.f;
    float mrun[2] = {-1e30f, -1e30f};
    float lrun[2] = {0.f, 0.f};
    const float scale = 0.125f;

    const unsigned long long* mrow0 =
        g_mbits + ((size_t)b * L_ + qt * QR + w * 16 + rr) * NCH;
    const unsigned long long* mrow1 = mrow0 + 8 * NCH;   // +8 q rows

    for (int ch = 0; ch < NCH; ch++) {
        const int m0 = ch * KT;
        __syncthreads();   // previous chunk's Ks/Vs consumers done

        // ---- stage K raw: Ks[d][j] = k[d][m0+j]
        #pragma unroll
        for (int it = 0; it < 4; it++) {
            int i = it * NTHR + tid;          // 64 d x 16 float4
            int d = i >> 4;
            int j = (i & 15) * 4;
            *(float4*)(Ks + d * 72 + j) =
                *(const float4*)(kg + (size_t)d * L_ + m0 + j);
        }
        // ---- stage V raw: Vs[j][d] = v[m0+j][d]
        #pragma unroll
        for (int it = 0; it < 4; it++) {
            int i = it * NTHR + tid;
            int j = i >> 4;
            int d = (i & 15) * 4;
            *(float4*)(Vs + j * 72 + d) =
                *(const float4*)(vg + (size_t)(m0 + j) * D_ + d);
        }
        __syncthreads();

        unsigned long long mb0 = mrow0[ch];
        unsigned long long mb1 = mrow1[ch];

        // ---- QK: 3xTF32 (hi*lo + lo*hi + hi*hi), hi/lo split at frag load
        #pragma unroll
        for (int nt = 0; nt < 8; nt++)
            #pragma unroll
            for (int e = 0; e < 4; e++) sacc[nt][e] = 0.f;

        #pragma unroll
        for (int kk = 0; kk < 8; kk++) {
            const int r = w * 16 + rr;
            const int c = kk * 8 + cc;
            float a0 = Qs[r * 68 + c];
            float a1 = Qs[(r + 8) * 68 + c];
            float a2 = Qs[r * 68 + c + 4];
            float a3 = Qs[(r + 8) * 68 + c + 4];
            float a0h = tf32hi(a0), a0l = a0 - a0h;
            float a1h = tf32hi(a1), a1l = a1 - a1h;
            float a2h = tf32hi(a2), a2l = a2 - a2h;
            float a3h = tf32hi(a3), a3l = a3 - a3h;
            #pragma unroll
            for (int nt = 0; nt < 8; nt++) {
                float b0 = Ks[(kk * 8 + cc) * 72 + nt * 8 + rr];
                float b1 = Ks[(kk * 8 + cc + 4) * 72 + nt * 8 + rr];
                float b0h = tf32hi(b0), b0l = b0 - b0h;
                float b1h = tf32hi(b1), b1l = b1 - b1h;
                mma_tf32(sacc[nt], a0h, a1h, a2h, a3h, b0l, b1l);  // hi*lo
                mma_tf32(sacc[nt], a0l, a1l, a2l, a3l, b0h, b1h);  // lo*hi
                mma_tf32(sacc[nt], a0h, a1h, a2h, a3h, b0h, b1h);  // hi*hi
            }
        }

        // ---- mask + scale + online softmax + P (rounded) to SMEM
        #pragma unroll
        for (int h = 0; h < 2; h++) {
            const unsigned long long mb = h ? mb1 : mb0;
            const int lr = w * 16 + h * 8 + rr;
            float mx = -1e30f;
            #pragma unroll
            for (int nt = 0; nt < 8; nt++) {
                int j0 = nt * 8 + 2 * cc;
                float s0 = sacc[nt][h * 2 + 0];
                float s1 = sacc[nt][h * 2 + 1];
                s0 = ((mb >> j0) & 1ull)       ? -1e30f : s0 * scale;
                s1 = ((mb >> (j0 + 1)) & 1ull) ? -1e30f : s1 * scale;
                sacc[nt][h * 2 + 0] = s0;
                sacc[nt][h * 2 + 1] = s1;
                mx = fmaxf(mx, fmaxf(s0, s1));
            }
            mx = fmaxf(mx, __shfl_xor_sync(0xffffffffu, mx, 1, 4));
            mx = fmaxf(mx, __shfl_xor_sync(0xffffffffu, mx, 2, 4));
            float mnew = fmaxf(mrun[h], mx);
            float corr = __expf(mrun[h] - mnew);
            mrun[h] = mnew;
            float ls = 0.f;
            #pragma unroll
            for (int nt = 0; nt < 8; nt++) {
                float p0 = __expf(sacc[nt][h * 2 + 0] - mnew);
                float p1 = __expf(sacc[nt][h * 2 + 1] - mnew);
                ls += p0 + p1;
                *(float2*)(Ps + lr * 68 + nt * 8 + 2 * cc) =
                    make_float2(tf32rna(p0), tf32rna(p1));
            }
            ls += __shfl_xor_sync(0xffffffffu, ls, 1, 4);
            ls += __shfl_xor_sync(0xffffffffu, ls, 2, 4);
            lrun[h] = lrun[h] * corr + ls;
            #pragma unroll
            for (int nt = 0; nt < 8; nt++) {
                oacc[nt][h * 2 + 0] *= corr;
                oacc[nt][h * 2 + 1] *= corr;
            }
        }
        __syncwarp();   // P rows are warp-private

        // ---- PV: out += P x V (V tf32-rounded at frag load)
        #pragma unroll
        for (int jj = 0; jj < 8; jj++) {
            const int r = w * 16 + rr;
            const int c = jj * 8 + cc;
            float p0 = Ps[r * 68 + c];
            float p1 = Ps[(r + 8) * 68 + c];
            float p2 = Ps[r * 68 + c + 4];
            float p3 = Ps[(r + 8) * 68 + c + 4];
            #pragma unroll
            for (int nt = 0; nt < 8; nt++) {
                float b0 = tf32rna(Vs[(jj * 8 + cc) * 72 + nt * 8 + rr]);
                float b1 = tf32rna(Vs[(jj * 8 + cc + 4) * 72 + nt * 8 + rr]);
                mma_tf32(oacc[nt], p0, p1, p2, p3, b0, b1);
            }
        }
    }

    // ---- epilogue: normalize + store
    #pragma unroll
    for (int h = 0; h < 2; h++) {
        float inv = 1.f / lrun[h];
        int grow = qt * QR + w * 16 + h * 8 + rr;
        float* og = O + ((size_t)gh * L_ + grow) * D_;
        #pragma unroll
        for (int nt = 0; nt < 8; nt++) {
            float2 t;
            t.x = oacc[nt][h * 2 + 0] * inv;
            t.y = oacc[nt][h * 2 + 1] * inv;
            *(float2*)(og + nt * 8 + 2 * cc) = t;
        }
    }
}

extern "C" void kernel_launch(void* const* d_in, const int* in_sizes, int n_in,
                              void* d_out, int out_size)
{
    const float* q = (const float*)d_in[0];
    const float* k = (const float*)d_in[1];
    const float* v = (const float*)d_in[2];
    const unsigned char* m = (const unsigned char*)d_in[3];
    float* o = (float*)d_out;

    cudaFuncSetAttribute(attn_fwd_mma2,
                         cudaFuncAttributeMaxDynamicSharedMemorySize,
                         SMEM_BYTES);

    detect_mask_dtype<<<1, 256>>>((const unsigned int*)m);
    pack_mask<<<(H_ * L_ * NCH) / 256, 256>>>(m);

    dim3 grid(L_ / QR, 32 * H_);   // (4, 256)
    attn_fwd_mma2<<<grid, NTHR, SMEM_BYTES>>>(q, k, v, o);
}

// round 14
// speedup vs baseline: 3.0848x; 1.0611x over previous
#include <cuda_runtime.h>
#include <cstdint>

// q: (32, 8, 512, 64) f32   k: (32, 8, 64, 512) f32   v: (32, 8, 512, 64) f32
// attn_mask: (8, 512, 512) bool (u8 vs i32 detected at runtime); True => -inf
// out: (32, 8, 512, 64) f32
static constexpr int H_   = 8;
static constexpr int C_   = 4;
static constexpr int L_   = 512;
static constexpr int D_   = 64;
static constexpr int QR   = 128;       // q rows per CTA (8 warps x 16 rows)
static constexpr int KT   = 64;        // keys per chunk
static constexpr int NCH  = L_ / KT;   // 8
static constexpr int NTHR = 256;

// SMEM (floats):
//  Qs[128][68]      raw q, row-major (frag reads conflict-free)
//  Ks[2][64][72]    raw k, d-major, double-buffered (cp.async)
//  Vs[2][64][72]    raw v, j-major, double-buffered (cp.async)
static constexpr int QS_OFF  = 0;
static constexpr int KBUF_F  = 64 * 72;
static constexpr int KS_OFF  = QS_OFF + 128 * 68;
static constexpr int VS_OFF  = KS_OFF + 2 * KBUF_F;
static constexpr int SMEM_FLOATS = VS_OFF + 2 * KBUF_F;
static constexpr int SMEM_BYTES  = SMEM_FLOATS * 4;   // 108544 B -> 2 CTAs/SM

extern __shared__ float smem_f[];

// 0 = mask elements are int32, 1 = packed uint8.
__device__ int g_mask_is_u8;
// Packed mask bits: [b][row][chunk] -> u64, bit j = key (chunk*64+j) masked.
__device__ unsigned long long g_mbits[H_ * L_ * NCH];

__global__ void detect_mask_dtype(const unsigned int* __restrict__ M32)
{
    __shared__ int found;
    if (threadIdx.x == 0) found = 0;
    __syncthreads();
    unsigned int w = M32[threadIdx.x];   // int32 bools are always 0 or 1
    if (w > 1u) atomicOr(&found, 1);
    __syncthreads();
    if (threadIdx.x == 0) g_mask_is_u8 = found;
}

__global__ void pack_mask(const unsigned char* __restrict__ M)
{
    int idx = blockIdx.x * blockDim.x + threadIdx.x;   // 0 .. 8*512*8-1
    int ch  = idx & 7;
    int row = idx >> 3;                                // b*512 + l
    unsigned long long bits = 0ull;
    if (g_mask_is_u8) {
        const unsigned char* p = M + (size_t)row * L_ + ch * 64;
        #pragma unroll
        for (int w = 0; w < 4; w++) {
            uint4 t = ((const uint4*)p)[w];
            unsigned int ws[4] = {t.x, t.y, t.z, t.w};
            #pragma unroll
            for (int e = 0; e < 4; e++)
                #pragma unroll
                for (int bq = 0; bq < 4; bq++)
                    if ((ws[e] >> (bq * 8)) & 0xFF)
                        bits |= 1ull << (w * 16 + e * 4 + bq);
        }
    } else {
        const int* p = (const int*)M + (size_t)row * L_ + ch * 64;
        #pragma unroll
        for (int w = 0; w < 16; w++) {
            int4 t = ((const int4*)p)[w];
            if (t.x) bits |= 1ull << (w * 4 + 0);
            if (t.y) bits |= 1ull << (w * 4 + 1);
            if (t.z) bits |= 1ull << (w * 4 + 2);
            if (t.w) bits |= 1ull << (w * 4 + 3);
        }
    }
    g_mbits[idx] = bits;
}

__device__ __forceinline__ float tf32hi(float x) {
    return __uint_as_float(__float_as_uint(x) & 0xFFFFE000u);
}
__device__ __forceinline__ float tf32rna(float x) {
    uint32_t u;
    asm("cvt.rna.tf32.f32 %0, %1;" : "=r"(u) : "f"(x));
    return __uint_as_float(u);
}
__device__ __forceinline__ void mma_tf32(float c[4],
                                         float a0, float a1, float a2, float a3,
                                         float b0, float b1)
{
    asm volatile(
        "mma.sync.aligned.m16n8k8.row.col.f32.tf32.tf32.f32 "
        "{%0,%1,%2,%3}, {%4,%5,%6,%7}, {%8,%9}, {%0,%1,%2,%3};\n"
        : "+f"(c[0]), "+f"(c[1]), "+f"(c[2]), "+f"(c[3])
        : "r"(__float_as_uint(a0)), "r"(__float_as_uint(a1)),
          "r"(__float_as_uint(a2)), "r"(__float_as_uint(a3)),
          "r"(__float_as_uint(b0)), "r"(__float_as_uint(b1)));
}
__device__ __forceinline__ void cp16(uint32_t dst, const void* src)
{
    asm volatile("cp.async.cg.shared.global [%0], [%1], 16;\n"
                 :: "r"(dst), "l"(src));
}

__global__ __launch_bounds__(NTHR, 2)
void attn_fwd_mma3(const float* __restrict__ Q,
                   const float* __restrict__ K,
                   const float* __restrict__ V,
                   float* __restrict__ O)
{
    float* Qs = smem_f + QS_OFF;

    const int qt   = blockIdx.x;         // 0..3
    const int gh   = blockIdx.y;         // 0..255
    const int b    = (gh / H_) / C_;
    const int tid  = threadIdx.x;
    const int w    = tid >> 5;           // warp 0..7 -> rows w*16..+15
    const int lane = tid & 31;
    const int rr   = lane >> 2;          // 0..7
    const int cc   = lane & 3;           // 0..3

    uint32_t smem_u32;
    {
        uint32_t a;
        asm("{ .reg .u64 t; cvta.to.shared.u64 t, %1; cvt.u32.u64 %0, t; }"
            : "=r"(a) : "l"(smem_f));
        smem_u32 = a;
    }

    const float* qg = Q + (size_t)gh * L_ * D_;
    const float* kg = K + (size_t)gh * D_ * L_;
    const float* vg = V + (size_t)gh * L_ * D_;

    // ---- prefetch Q (once) + K/V chunk 0 into buffer 0 (group 0)
    {
        #pragma unroll
        for (int it = 0; it < 8; it++) {          // Q: 2048 float4
            int i = it * NTHR + tid;
            int r = i >> 4;
            int c = (i & 15) * 4;
            cp16(smem_u32 + (QS_OFF + r * 68 + c) * 4,
                 qg + (size_t)qt * QR * D_ + i * 4);
        }
        #pragma unroll
        for (int it = 0; it < 4; it++) {          // K ch0
            int i = it * NTHR + tid;
            int d = i >> 4;
            int j = (i & 15) * 4;
            cp16(smem_u32 + (KS_OFF + d * 72 + j) * 4,
                 kg + (size_t)d * L_ + j);
        }
        #pragma unroll
        for (int it = 0; it < 4; it++) {          // V ch0
            int i = it * NTHR + tid;
            int j = i >> 4;
            int d = (i & 15) * 4;
            cp16(smem_u32 + (VS_OFF + j * 72 + d) * 4,
                 vg + (size_t)j * D_ + d);
        }
        asm volatile("cp.async.commit_group;\n");
    }

    float sacc[8][4];
    float oacc[8][4];
    #pragma unroll
    for (int nt = 0; nt < 8; nt++)
        #pragma unroll
        for (int e = 0; e < 4; e++) oacc[nt][e] = 0.f;
    float mrun[2] = {-1e30f, -1e30f};
    float lrun[2] = {0.f, 0.f};
    const float scale = 0.125f;

    const unsigned long long* mrow0 =
        g_mbits + ((size_t)b * L_ + qt * QR + w * 16 + rr) * NCH;
    const unsigned long long* mrow1 = mrow0 + 8 * NCH;   // +8 q rows

    const int src_a = (lane & 28) | (cc >> 1);   // (rr<<2)|(cc>>1)
    const int src_b = src_a + 2;
    const bool oddc = cc & 1;

    for (int ch = 0; ch < NCH; ch++) {
        float* Ks = smem_f + KS_OFF + (ch & 1) * KBUF_F;
        float* Vs = smem_f + VS_OFF + (ch & 1) * KBUF_F;

        __syncthreads();   // all warps done reading buf[(ch+1)&1] (prev cur)

        if (ch + 1 < NCH) {          // prefetch next chunk into other buffer
            const int nb = (ch + 1) & 1;
            const int m1 = (ch + 1) * KT;
            #pragma unroll
            for (int it = 0; it < 4; it++) {
                int i = it * NTHR + tid;
                int d = i >> 4;
                int j = (i & 15) * 4;
                cp16(smem_u32 + (KS_OFF + nb * KBUF_F + d * 72 + j) * 4,
                     kg + (size_t)d * L_ + m1 + j);
            }
            #pragma unroll
            for (int it = 0; it < 4; it++) {
                int i = it * NTHR + tid;
                int j = i >> 4;
                int d = (i & 15) * 4;
                cp16(smem_u32 + (VS_OFF + nb * KBUF_F + j * 72 + d) * 4,
                     vg + (size_t)(m1 + j) * D_ + d);
            }
            asm volatile("cp.async.commit_group;\n");
            asm volatile("cp.async.wait_group 1;\n");
        } else {
            asm volatile("cp.async.wait_group 0;\n");
        }
        __syncthreads();   // cur staging visible to all threads

        unsigned long long mb0 = mrow0[ch];
        unsigned long long mb1 = mrow1[ch];

        // ---- QK: 3xTF32 (hi*lo + lo*hi + hi*hi), hi/lo split at frag load
        #pragma unroll
        for (int nt = 0; nt < 8; nt++)
            #pragma unroll
            for (int e = 0; e < 4; e++) sacc[nt][e] = 0.f;

        #pragma unroll
        for (int kk = 0; kk < 8; kk++) {
            const int r = w * 16 + rr;
            const int c = kk * 8 + cc;
            float a0 = Qs[r * 68 + c];
            float a1 = Qs[(r + 8) * 68 + c];
            float a2 = Qs[r * 68 + c + 4];
            float a3 = Qs[(r + 8) * 68 + c + 4];
            float a0h = tf32hi(a0), a0l = a0 - a0h;
            float a1h = tf32hi(a1), a1l = a1 - a1h;
            float a2h = tf32hi(a2), a2l = a2 - a2h;
            float a3h = tf32hi(a3), a3l = a3 - a3h;
            #pragma unroll
            for (int nt = 0; nt < 8; nt++) {
                float b0 = Ks[(kk * 8 + cc) * 72 + nt * 8 + rr];
                float b1 = Ks[(kk * 8 + cc + 4) * 72 + nt * 8 + rr];
                float b0h = tf32hi(b0), b0l = b0 - b0h;
                float b1h = tf32hi(b1), b1l = b1 - b1h;
                mma_tf32(sacc[nt], a0h, a1h, a2h, a3h, b0l, b1l);  // hi*lo
                mma_tf32(sacc[nt], a0l, a1l, a2l, a3l, b0h, b1h);  // lo*hi
                mma_tf32(sacc[nt], a0h, a1h, a2h, a3h, b0h, b1h);  // hi*hi
            }
        }

        // ---- mask + scale + online softmax; P kept in sacc (rna-rounded)
        #pragma unroll
        for (int h = 0; h < 2; h++) {
            const unsigned long long mb = h ? mb1 : mb0;
            float mx = -1e30f;
            #pragma unroll
            for (int nt = 0; nt < 8; nt++) {
                int j0 = nt * 8 + 2 * cc;
                float s0 = sacc[nt][h * 2 + 0];
                float s1 = sacc[nt][h * 2 + 1];
                s0 = ((mb >> j0) & 1ull)       ? -1e30f : s0 * scale;
                s1 = ((mb >> (j0 + 1)) & 1ull) ? -1e30f : s1 * scale;
                sacc[nt][h * 2 + 0] = s0;
                sacc[nt][h * 2 + 1] = s1;
                mx = fmaxf(mx, fmaxf(s0, s1));
            }
            mx = fmaxf(mx, __shfl_xor_sync(0xffffffffu, mx, 1, 4));
            mx = fmaxf(mx, __shfl_xor_sync(0xffffffffu, mx, 2, 4));
            float mnew = fmaxf(mrun[h], mx);
            float corr = __expf(mrun[h] - mnew);
            mrun[h] = mnew;
            float ls = 0.f;
            #pragma unroll
            for (int nt = 0; nt < 8; nt++) {
                float p0 = __expf(sacc[nt][h * 2 + 0] - mnew);
                float p1 = __expf(sacc[nt][h * 2 + 1] - mnew);
                ls += p0 + p1;
                sacc[nt][h * 2 + 0] = tf32rna(p0);
                sacc[nt][h * 2 + 1] = tf32rna(p1);
            }
            ls += __shfl_xor_sync(0xffffffffu, ls, 1, 4);
            ls += __shfl_xor_sync(0xffffffffu, ls, 2, 4);
            lrun[h] = lrun[h] * corr + ls;
            #pragma unroll
            for (int nt = 0; nt < 8; nt++) {
                oacc[nt][h * 2 + 0] *= corr;
                oacc[nt][h * 2 + 1] *= corr;
            }
        }

        // ---- PV: out += P x V; P acc-layout -> A-frag via intra-warp shfl
        #pragma unroll
        for (int jj = 0; jj < 8; jj++) {
            float e0 = sacc[jj][0], e1 = sacc[jj][1];
            float e2 = sacc[jj][2], e3 = sacc[jj][3];
            float x00 = __shfl_sync(0xffffffffu, e0, src_a, 32);
            float x01 = __shfl_sync(0xffffffffu, e1, src_a, 32);
            float x10 = __shfl_sync(0xffffffffu, e2, src_a, 32);
            float x11 = __shfl_sync(0xffffffffu, e3, src_a, 32);
            float x20 = __shfl_sync(0xffffffffu, e0, src_b, 32);
            float x21 = __shfl_sync(0xffffffffu, e1, src_b, 32);
            float x30 = __shfl_sync(0xffffffffu, e2, src_b, 32);
            float x31 = __shfl_sync(0xffffffffu, e3, src_b, 32);
            float p0 = oddc ? x01 : x00;   // P[r   ][jj*8+cc]
            float p1 = oddc ? x11 : x10;   // P[r+8 ][jj*8+cc]
            float p2 = oddc ? x21 : x20;   // P[r   ][jj*8+cc+4]
            float p3 = oddc ? x31 : x30;   // P[r+8 ][jj*8+cc+4]
            #pragma unroll
            for (int nt = 0; nt < 8; nt++) {
                float b0 = tf32rna(Vs[(jj * 8 + cc) * 72 + nt * 8 + rr]);
                float b1 = tf32rna(Vs[(jj * 8 + cc + 4) * 72 + nt * 8 + rr]);
                mma_tf32(oacc[nt], p0, p1, p2, p3, b0, b1);
            }
        }
    }

    // ---- epilogue: normalize + store
    #pragma unroll
    for (int h = 0; h < 2; h++) {
        float inv = 1.f / lrun[h];
        int grow = qt * QR + w * 16 + h * 8 + rr;
        float* og = O + ((size_t)gh * L_ + grow) * D_;
        #pragma unroll
        for (int nt = 0; nt < 8; nt++) {
            float2 t;
            t.x = oacc[nt][h * 2 + 0] * inv;
            t.y = oacc[nt][h * 2 + 1] * inv;
            *(float2*)(og + nt * 8 + 2 * cc) = t;
        }
    }
}

extern "C" void kernel_launch(void* const* d_in, const int* in_sizes, int n_in,
                              void* d_out, int out_size)
{
    const float* q = (const float*)d_in[0];
    const float* k = (const float*)d_in[1];
    const float* v = (const float*)d_in[2];
    const unsigned char* m = (const unsigned char*)d_in[3];
    float* o = (float*)d_out;

    cudaFuncSetAttribute(attn_fwd_mma3,
                         cudaFuncAttributeMaxDynamicSharedMemorySize,
                         SMEM_BYTES);

    detect_mask_dtype<<<1, 256>>>((const unsigned int*)m);
    pack_mask<<<(H_ * L_ * NCH) / 256, 256>>>(m);

    dim3 grid(L_ / QR, 32 * H_);   // (4, 256)
    attn_fwd_mma3<<<grid, NTHR, SMEM_BYTES>>>(q, k, v, o);
}

// round 16
// speedup vs baseline: 3.8286x; 1.2411x over previous
#include <cuda_runtime.h>
#include <cstdint>

// q: (32, 8, 512, 64) f32   k: (32, 8, 64, 512) f32   v: (32, 8, 512, 64) f32
// attn_mask: (8, 512, 512) bool (u8 vs i32, detected inside pack_mask); True => -inf
// out: (32, 8, 512, 64) f32
static constexpr int H_   = 8;
static constexpr int C_   = 4;
static constexpr int L_   = 512;
static constexpr int D_   = 64;
static constexpr int QR   = 128;       // q rows per CTA (8 warps x 16 rows)
static constexpr int KT   = 64;        // keys per chunk
static constexpr int NCH  = L_ / KT;   // 8
static constexpr int NTHR = 256;

// SMEM (floats):
//  Qs[128][68]      raw q, row-major (frag reads conflict-free)
//  Ks[2][64][72]    raw k, d-major, double-buffered (cp.async)
//  Vs[2][64][72]    raw v, j-major, double-buffered (cp.async)
static constexpr int QS_OFF  = 0;
static constexpr int KBUF_F  = 64 * 72;
static constexpr int KS_OFF  = QS_OFF + 128 * 68;
static constexpr int VS_OFF  = KS_OFF + 2 * KBUF_F;
static constexpr int SMEM_FLOATS = VS_OFF + 2 * KBUF_F;
static constexpr int SMEM_BYTES  = SMEM_FLOATS * 4;   // 108544 B -> 2 CTAs/SM

extern __shared__ float smem_f[];

// Packed mask bits: [b][row][chunk] -> u64, bit j = key (chunk*64+j) masked.
__device__ unsigned long long g_mbits[H_ * L_ * NCH];

// One kernel: detects dtype (block-locally, 8192-word vote) and packs bits.
// int32 bool words are always 0/1; u8 bool words exceed 1 unless the 4-byte
// pattern is (0,0,0,0)/(1,0,0,0) (p=1/8/word) -> P(block miss) = 8^-8192 ~ 0.
__global__ void pack_mask(const unsigned char* __restrict__ M)
{
    __shared__ int blk_u8;
    if (threadIdx.x == 0) blk_u8 = 0;
    __syncthreads();

    int idx = blockIdx.x * blockDim.x + threadIdx.x;   // 0 .. 8*512*8-1
    int ch  = idx & 7;
    int row = idx >> 3;                                // b*512 + l

    // Candidate u8 region for this thread (always in-bounds for both dtypes)
    const unsigned char* p8 = M + (size_t)row * L_ + ch * 64;
    uint4 w8[4];
    #pragma unroll
    for (int w = 0; w < 4; w++) w8[w] = ((const uint4*)p8)[w];

    int has = 0;
    #pragma unroll
    for (int w = 0; w < 4; w++)
        if (w8[w].x > 1u || w8[w].y > 1u || w8[w].z > 1u || w8[w].w > 1u)
            has = 1;
    if (has) blk_u8 = 1;      // benign race, all writers write 1
    __syncthreads();

    unsigned long long bits = 0ull;
    if (blk_u8) {
        #pragma unroll
        for (int w = 0; w < 4; w++) {
            unsigned int ws[4] = {w8[w].x, w8[w].y, w8[w].z, w8[w].w};
            #pragma unroll
            for (int e = 0; e < 4; e++)
                #pragma unroll
                for (int bq = 0; bq < 4; bq++)
                    if ((ws[e] >> (bq * 8)) & 0xFF)
                        bits |= 1ull << (w * 16 + e * 4 + bq);
        }
    } else {
        const int* p = (const int*)M + (size_t)row * L_ + ch * 64;
        #pragma unroll
        for (int w = 0; w < 16; w++) {
            int4 t = ((const int4*)p)[w];
            if (t.x) bits |= 1ull << (w * 4 + 0);
            if (t.y) bits |= 1ull << (w * 4 + 1);
            if (t.z) bits |= 1ull << (w * 4 + 2);
            if (t.w) bits |= 1ull << (w * 4 + 3);
        }
    }
    g_mbits[idx] = bits;
}

__device__ __forceinline__ float tf32hi(float x) {
    return __uint_as_float(__float_as_uint(x) & 0xFFFFE000u);
}
__device__ __forceinline__ float tf32rna(float x) {
    uint32_t u;
    asm("cvt.rna.tf32.f32 %0, %1;" : "=r"(u) : "f"(x));
    return __uint_as_float(u);
}
__device__ __forceinline__ void mma_tf32(float c[4],
                                         float a0, float a1, float a2, float a3,
                                         float b0, float b1)
{
    asm volatile(
        "mma.sync.aligned.m16n8k8.row.col.f32.tf32.tf32.f32 "
        "{%0,%1,%2,%3}, {%4,%5,%6,%7}, {%8,%9}, {%0,%1,%2,%3};\n"
        : "+f"(c[0]), "+f"(c[1]), "+f"(c[2]), "+f"(c[3])
        : "r"(__float_as_uint(a0)), "r"(__float_as_uint(a1)),
          "r"(__float_as_uint(a2)), "r"(__float_as_uint(a3)),
          "r"(__float_as_uint(b0)), "r"(__float_as_uint(b1)));
}
__device__ __forceinline__ void cp16(uint32_t dst, const void* src)
{
    asm volatile("cp.async.cg.shared.global [%0], [%1], 16;\n"
                 :: "r"(dst), "l"(src));
}

__global__ __launch_bounds__(NTHR, 2)
void attn_fwd_mma4(const float* __restrict__ Q,
                   const float* __restrict__ K,
                   const float* __restrict__ V,
                   float* __restrict__ O)
{
    float* Qs = smem_f + QS_OFF;

    const int qt   = blockIdx.x;         // 0..3
    const int gh   = blockIdx.y;         // 0..255
    const int b    = (gh / H_) / C_;
    const int tid  = threadIdx.x;
    const int w    = tid >> 5;           // warp 0..7 -> rows w*16..+15
    const int lane = tid & 31;
    const int rr   = lane >> 2;          // 0..7
    const int cc   = lane & 3;           // 0..3

    uint32_t smem_u32;
    {
        uint32_t a;
        asm("{ .reg .u64 t; cvta.to.shared.u64 t, %1; cvt.u32.u64 %0, t; }"
            : "=r"(a) : "l"(smem_f));
        smem_u32 = a;
    }

    const float* qg = Q + (size_t)gh * L_ * D_;
    const float* kg = K + (size_t)gh * D_ * L_;
    const float* vg = V + (size_t)gh * L_ * D_;

    // ---- prefetch Q (once) + K/V chunk 0 into buffer 0 (group 0)
    {
        #pragma unroll
        for (int it = 0; it < 8; it++) {          // Q: 2048 float4
            int i = it * NTHR + tid;
            int r = i >> 4;
            int c = (i & 15) * 4;
            cp16(smem_u32 + (QS_OFF + r * 68 + c) * 4,
                 qg + (size_t)qt * QR * D_ + i * 4);
        }
        #pragma unroll
        for (int it = 0; it < 4; it++) {          // K ch0
            int i = it * NTHR + tid;
            int d = i >> 4;
            int j = (i & 15) * 4;
            cp16(smem_u32 + (KS_OFF + d * 72 + j) * 4,
                 kg + (size_t)d * L_ + j);
        }
        #pragma unroll
        for (int it = 0; it < 4; it++) {          // V ch0
            int i = it * NTHR + tid;
            int j = i >> 4;
            int d = (i & 15) * 4;
            cp16(smem_u32 + (VS_OFF + j * 72 + d) * 4,
                 vg + (size_t)j * D_ + d);
        }
        asm volatile("cp.async.commit_group;\n");
    }

    float sacc[8][4];
    float oacc[8][4];
    #pragma unroll
    for (int nt = 0; nt < 8; nt++)
        #pragma unroll
        for (int e = 0; e < 4; e++) oacc[nt][e] = 0.f;
    float mrun[2] = {-1e30f, -1e30f};
    float lrun[2] = {0.f, 0.f};
    const float scale = 0.125f;

    const unsigned long long* mrow0 =
        g_mbits + ((size_t)b * L_ + qt * QR + w * 16 + rr) * NCH;
    const unsigned long long* mrow1 = mrow0 + 8 * NCH;   // +8 q rows

    const int src_a = (lane & 28) | (cc >> 1);   // (rr<<2)|(cc>>1)
    const int src_b = src_a + 2;
    const bool oddc = cc & 1;

    for (int ch = 0; ch < NCH; ch++) {
        float* Ks = smem_f + KS_OFF + (ch & 1) * KBUF_F;
        float* Vs = smem_f + VS_OFF + (ch & 1) * KBUF_F;

        __syncthreads();   // all warps done reading buf[(ch+1)&1] (prev cur)

        if (ch + 1 < NCH) {          // prefetch next chunk into other buffer
            const int nb = (ch + 1) & 1;
            const int m1 = (ch + 1) * KT;
            #pragma unroll
            for (int it = 0; it < 4; it++) {
                int i = it * NTHR + tid;
                int d = i >> 4;
                int j = (i & 15) * 4;
                cp16(smem_u32 + (KS_OFF + nb * KBUF_F + d * 72 + j) * 4,
                     kg + (size_t)d * L_ + m1 + j);
            }
            #pragma unroll
            for (int it = 0; it < 4; it++) {
                int i = it * NTHR + tid;
                int j = i >> 4;
                int d = (i & 15) * 4;
                cp16(smem_u32 + (VS_OFF + nb * KBUF_F + j * 72 + d) * 4,
                     vg + (size_t)(m1 + j) * D_ + d);
            }
            asm volatile("cp.async.commit_group;\n");
            asm volatile("cp.async.wait_group 1;\n");
        } else {
            asm volatile("cp.async.wait_group 0;\n");
        }
        __syncthreads();   // cur staging visible to all threads

        unsigned long long mb0 = mrow0[ch];
        unsigned long long mb1 = mrow1[ch];

        // ---- QK: 2xTF32 (lo*hi + hi*hi); B side uses hi only
        #pragma unroll
        for (int nt = 0; nt < 8; nt++)
            #pragma unroll
            for (int e = 0; e < 4; e++) sacc[nt][e] = 0.f;

        #pragma unroll
        for (int kk = 0; kk < 8; kk++) {
            const int r = w * 16 + rr;
            const int c = kk * 8 + cc;
            float a0 = Qs[r * 68 + c];
            float a1 = Qs[(r + 8) * 68 + c];
            float a2 = Qs[r * 68 + c + 4];
            float a3 = Qs[(r + 8) * 68 + c + 4];
            float a0h = tf32hi(a0), a0l = a0 - a0h;
            float a1h = tf32hi(a1), a1l = a1 - a1h;
            float a2h = tf32hi(a2), a2l = a2 - a2h;
            float a3h = tf32hi(a3), a3l = a3 - a3h;
            #pragma unroll
            for (int nt = 0; nt < 8; nt++) {
                float b0h = tf32hi(Ks[(kk * 8 + cc) * 72 + nt * 8 + rr]);
                float b1h = tf32hi(Ks[(kk * 8 + cc + 4) * 72 + nt * 8 + rr]);
                mma_tf32(sacc[nt], a0l, a1l, a2l, a3l, b0h, b1h);  // lo*hi
                mma_tf32(sacc[nt], a0h, a1h, a2h, a3h, b0h, b1h);  // hi*hi
            }
        }

        // ---- mask + scale + online softmax; P kept in sacc (rna-rounded)
        #pragma unroll
        for (int h = 0; h < 2; h++) {
            const unsigned long long mb = h ? mb1 : mb0;
            float mx = -1e30f;
            #pragma unroll
            for (int nt = 0; nt < 8; nt++) {
                int j0 = nt * 8 + 2 * cc;
                float s0 = sacc[nt][h * 2 + 0];
                float s1 = sacc[nt][h * 2 + 1];
                s0 = ((mb >> j0) & 1ull)       ? -1e30f : s0 * scale;
                s1 = ((mb >> (j0 + 1)) & 1ull) ? -1e30f : s1 * scale;
                sacc[nt][h * 2 + 0] = s0;
                sacc[nt][h * 2 + 1] = s1;
                mx = fmaxf(mx, fmaxf(s0, s1));
            }
            mx = fmaxf(mx, __shfl_xor_sync(0xffffffffu, mx, 1, 4));
            mx = fmaxf(mx, __shfl_xor_sync(0xffffffffu, mx, 2, 4));
            float mnew = fmaxf(mrun[h], mx);
            float corr = __expf(mrun[h] - mnew);
            mrun[h] = mnew;
            float ls = 0.f;
            #pragma unroll
            for (int nt = 0; nt < 8; nt++) {
                float p0 = __expf(sacc[nt][h * 2 + 0] - mnew);
                float p1 = __expf(sacc[nt][h * 2 + 1] - mnew);
                ls += p0 + p1;
                sacc[nt][h * 2 + 0] = tf32rna(p0);
                sacc[nt][h * 2 + 1] = tf32rna(p1);
            }
            ls += __shfl_xor_sync(0xffffffffu, ls, 1, 4);
            ls += __shfl_xor_sync(0xffffffffu, ls, 2, 4);
            lrun[h] = lrun[h] * corr + ls;
            #pragma unroll
            for (int nt = 0; nt < 8; nt++) {
                oacc[nt][h * 2 + 0] *= corr;
                oacc[nt][h * 2 + 1] *= corr;
            }
        }

        // ---- PV: out += P x V; P acc-layout -> A-frag via intra-warp shfl
        #pragma unroll
        for (int jj = 0; jj < 8; jj++) {
            float e0 = sacc[jj][0], e1 = sacc[jj][1];
            float e2 = sacc[jj][2], e3 = sacc[jj][3];
            float x00 = __shfl_sync(0xffffffffu, e0, src_a, 32);
            float x01 = __shfl_sync(0xffffffffu, e1, src_a, 32);
            float x10 = __shfl_sync(0xffffffffu, e2, src_a, 32);
            float x11 = __shfl_sync(0xffffffffu, e3, src_a, 32);
            float x20 = __shfl_sync(0xffffffffu, e0, src_b, 32);
            float x21 = __shfl_sync(0xffffffffu, e1, src_b, 32);
            float x30 = __shfl_sync(0xffffffffu, e2, src_b, 32);
            float x31 = __shfl_sync(0xffffffffu, e3, src_b, 32);
            float p0 = oddc ? x01 : x00;   // P[r   ][jj*8+cc]
            float p1 = oddc ? x11 : x10;   // P[r+8 ][jj*8+cc]
            float p2 = oddc ? x21 : x20;   // P[r   ][jj*8+cc+4]
            float p3 = oddc ? x31 : x30;   // P[r+8 ][jj*8+cc+4]
            #pragma unroll
            for (int nt = 0; nt < 8; nt++) {
                float b0 = tf32rna(Vs[(jj * 8 + cc) * 72 + nt * 8 + rr]);
                float b1 = tf32rna(Vs[(jj * 8 + cc + 4) * 72 + nt * 8 + rr]);
                mma_tf32(oacc[nt], p0, p1, p2, p3, b0, b1);
            }
        }
    }

    // ---- epilogue: normalize + store
    #pragma unroll
    for (int h = 0; h < 2; h++) {
        float inv = 1.f / lrun[h];
        int grow = qt * QR + w * 16 + h * 8 + rr;
        float* og = O + ((size_t)gh * L_ + grow) * D_;
        #pragma unroll
        for (int nt = 0; nt < 8; nt++) {
            float2 t;
            t.x = oacc[nt][h * 2 + 0] * inv;
            t.y = oacc[nt][h * 2 + 1] * inv;
            *(float2*)(og + nt * 8 + 2 * cc) = t;
        }
    }
}

extern "C" void kernel_launch(void* const* d_in, const int* in_sizes, int n_in,
                              void* d_out, int out_size)
{
    const float* q = (const float*)d_in[0];
    const float* k = (const float*)d_in[1];
    const float* v = (const float*)d_in[2];
    const unsigned char* m = (const unsigned char*)d_in[3];
    float* o = (float*)d_out;

    cudaFuncSetAttribute(attn_fwd_mma4,
                         cudaFuncAttributeMaxDynamicSharedMemorySize,
                         SMEM_BYTES);

    pack_mask<<<(H_ * L_ * NCH) / 256, 256>>>(m);

    dim3 grid(L_ / QR, 32 * H_);   // (4, 256)
    attn_fwd_mma4<<<grid, NTHR, SMEM_BYTES>>>(q, k, v, o);
}